// round 5
// baseline (speedup 1.0000x reference)
#include <cuda_runtime.h>
#include <cuda_bf16.h>
#include <cstdint>

// ============================================================================
// CrossAttentionBlock — 4-kernel split (sm_100a)
//   K0: pre-convert [g_w; th_w*log2e; ph_w] -> tf32(rna) bits   (1.5MB, ~3us)
//   K1: projections via cp.async 3-stage pipelined tf32 HMMA, occ=3
//   K2: y_i = sum_j 2^(ph_i*th_j) g_j / sum_j 2^(ph_i*th_j)   (MUFU-bound)
//   K3: out = y@W_w^T + W_b + x0
// ============================================================================

namespace {
constexpr int kB   = 16384;
constexpr int kC   = 1024;
constexpr int kD   = 128;
constexpr int kXStr  = 20;               // smem word stride (conflict-free)
constexpr int kW3Str = 132;              // K3 W-tile stride
constexpr float kLog2e = 1.4426950408889634f;
constexpr int kK3Smem = 128 * kW3Str * 4;      // 67584 B
// K1 smem: 3 stages x (A 128x20 + W 128x20) words
constexpr int kStageW   = 128 * kXStr;         // 2560 words per tile-stage
constexpr int kStageB   = kStageW * 4;         // 10240 bytes
constexpr int kWBaseW   = 3 * kStageW;         // word offset of W region (7680)
constexpr int kK1Smem   = 6 * kStageB;         // 61440 B
}  // namespace

// inter-kernel scratch
__device__ float    g_glob[kB * kD];
__device__ float    th_glob[kB * kD];   // pre-scaled by log2e
__device__ float    ph_glob[kB * kD];
__device__ float    y_glob[kB * kD];    // tf32 bit patterns
__device__ uint32_t w_glob[3 * kD * kC];  // tf32(rna) weights, th pre-scaled

__device__ __forceinline__ uint32_t f2tf(float f) {
    uint32_t u;
    asm("cvt.rna.tf32.f32 %0, %1;" : "=r"(u) : "f"(f));
    return u;
}
__device__ __forceinline__ float fast_ex2(float x) {
    float r;
    asm("ex2.approx.ftz.f32 %0, %1;" : "=f"(r) : "f"(x));
    return r;
}
__device__ __forceinline__ float fast_rcp(float x) {
    float r;
    asm("rcp.approx.ftz.f32 %0, %1;" : "=f"(r) : "f"(x));
    return r;
}
__device__ __forceinline__ void mma_tf32(float c[4],
                                         const uint32_t a[4],
                                         uint32_t b0, uint32_t b1) {
    asm volatile(
        "mma.sync.aligned.m16n8k8.row.col.f32.tf32.tf32.f32 "
        "{%0,%1,%2,%3},{%4,%5,%6,%7},{%8,%9},{%0,%1,%2,%3};"
        : "+f"(c[0]), "+f"(c[1]), "+f"(c[2]), "+f"(c[3])
        : "r"(a[0]), "r"(a[1]), "r"(a[2]), "r"(a[3]), "r"(b0), "r"(b1));
}
__device__ __forceinline__ void sts_tf4(uint32_t* dst, float4 v) {
    uint4 u;
    u.x = f2tf(v.x); u.y = f2tf(v.y); u.z = f2tf(v.z); u.w = f2tf(v.w);
    *reinterpret_cast<uint4*>(dst) = u;
}
__device__ __forceinline__ void cp16(uint32_t dst, const void* src) {
    asm volatile("cp.async.cg.shared.global [%0], [%1], 16;" :: "r"(dst), "l"(src));
}
__device__ __forceinline__ void cp_commit() {
    asm volatile("cp.async.commit_group;");
}
template <int N>
__device__ __forceinline__ void cp_wait() {
    asm volatile("cp.async.wait_group %0;" :: "n"(N));
}
__device__ __forceinline__ uint32_t smem_u32(const void* p) {
    uint32_t a;
    asm("{ .reg .u64 t; cvta.to.shared.u64 t, %1; cvt.u32.u64 %0, t; }"
        : "=r"(a) : "l"(p));
    return a;
}

// ===================== K0: weight pre-convert (tf32 rna) =====================
__global__ void __launch_bounds__(256)
conv_w_kernel(const float* __restrict__ g_w, const float* __restrict__ th_w,
              const float* __restrict__ ph_w) {
    int i4 = blockIdx.x * 256 + threadIdx.x;       // 0..98303 float4 slots
    int head = i4 >> 15;                            // 32768 float4 per head
    int loc  = i4 & 32767;
    const float4* src = (head == 0) ? reinterpret_cast<const float4*>(g_w)
                      : (head == 1) ? reinterpret_cast<const float4*>(th_w)
                                    : reinterpret_cast<const float4*>(ph_w);
    float4 v = src[loc];
    float s = (head == 1) ? kLog2e : 1.0f;
    uint4 u;
    u.x = f2tf(v.x * s); u.y = f2tf(v.y * s);
    u.z = f2tf(v.z * s); u.w = f2tf(v.w * s);
    reinterpret_cast<uint4*>(w_glob)[i4] = u;
}

// ========= K1: projections, cp.async 3-stage pipeline, tile 128x128 =========
// grid (128 B-tiles, 3 heads), 256 thr, 3 CTAs/SM (single wave of 384).
__global__ void __launch_bounds__(256, 3)
proj_kernel(const float* __restrict__ x0, const float* __restrict__ x1,
            const float* __restrict__ g_b, const float* __restrict__ th_b,
            const float* __restrict__ ph_b) {
    extern __shared__ uint32_t sm[];

    const int tid  = threadIdx.x;
    const int lane = tid & 31;
    const int wid  = tid >> 5;
    const int gid  = lane >> 2;
    const int tig  = lane & 3;
    const int wm   = wid >> 1;
    const int wn   = wid & 1;
    const int row0 = blockIdx.x * 128;
    const int by   = blockIdx.y;

    const float* A = (by == 0) ? x0 : x1;
    const uint32_t* W = w_glob + (size_t)by * kD * kC;

    // per-thread cp.async slots: rows r0 and r0+64, 4 floats at col c*4
    const int r0 = tid >> 2;
    const int c4 = (tid & 3) * 4;
    const float*    srcA = A + (size_t)(row0 + r0) * kC + c4;
    const uint32_t* srcW = W + (size_t)r0 * kC + c4;
    const uint32_t smemBase = smem_u32(sm);
    const uint32_t dA0 = smemBase + (r0 * kXStr + c4) * 4;
    const uint32_t dW0 = smemBase + kWBaseW * 4 + (r0 * kXStr + c4) * 4;
    const uint32_t kHalf = 64 * kXStr * 4;  // +64 rows in smem (5120 B)

    auto issue = [&](int stage, int kc) {
        const float*    pa = srcA + kc * 16;
        const uint32_t* pw = srcW + kc * 16;
        uint32_t sb = stage * kStageB;
        cp16(dA0 + sb, pa);
        cp16(dA0 + sb + kHalf, pa + 64 * kC);
        cp16(dW0 + sb, pw);
        cp16(dW0 + sb + kHalf, pw + 64 * kC);
        cp_commit();
    };

    issue(0, 0);
    issue(1, 1);

    float acc[2][8][4];
#pragma unroll
    for (int a = 0; a < 2; a++)
#pragma unroll
        for (int b = 0; b < 8; b++)
#pragma unroll
            for (int ci = 0; ci < 4; ci++) acc[a][b][ci] = 0.f;

    // per-thread fragment row offsets (words)
    const int aRow = (wm * 32 + gid) * kXStr + tig;
    const int bRow = kWBaseW + (wn * 64 + gid) * kXStr + tig;

    int buf = 0;
#pragma unroll 1
    for (int kc = 0; kc < 64; kc++) {
        if (kc < 62) cp_wait<1>(); else cp_wait<0>();
        __syncthreads();
        if (kc + 2 < 64) {
            int ns = buf + 2; if (ns >= 3) ns -= 3;
            issue(ns, kc + 2);
        }
        const uint32_t* aS = sm + buf * kStageW + aRow;
        const uint32_t* bS = sm + buf * kStageW + bRow;
#pragma unroll
        for (int ks = 0; ks < 2; ks++) {
            const int k = ks * 8;
            uint32_t a[2][4];
#pragma unroll
            for (int mt = 0; mt < 2; mt++) {
                const uint32_t* p = aS + mt * 16 * kXStr + k;
                a[mt][0] = p[0];
                a[mt][1] = p[8 * kXStr];
                a[mt][2] = p[4];
                a[mt][3] = p[8 * kXStr + 4];
            }
#pragma unroll
            for (int nt = 0; nt < 8; nt++) {
                const uint32_t* q = bS + nt * 8 * kXStr + k;
                uint32_t b0 = q[0];
                uint32_t b1 = q[4];
                mma_tf32(acc[0][nt], a[0], b0, b1);
                mma_tf32(acc[1][nt], a[1], b0, b1);
            }
        }
        buf++; if (buf == 3) buf = 0;
    }

    const float* bias = (by == 0) ? g_b : (by == 1) ? th_b : ph_b;
    const float bscale = (by == 1) ? kLog2e : 1.0f;
    float* outp = (by == 0) ? g_glob : (by == 1) ? th_glob : ph_glob;
#pragma unroll
    for (int mt = 0; mt < 2; mt++)
#pragma unroll
        for (int nt = 0; nt < 8; nt++)
#pragma unroll
            for (int ci = 0; ci < 4; ci++) {
                int r = wm * 32 + mt * 16 + gid + ((ci >= 2) ? 8 : 0);
                int n = wn * 64 + nt * 8 + tig * 2 + (ci & 1);
                outp[(size_t)(row0 + r) * kD + n] =
                    acc[mt][nt][ci] + bias[n] * bscale;
            }
}

// ========================= K2: attention (MUFU-bound) =========================
__global__ void __launch_bounds__(256)
attn_kernel() {
    __shared__ float tgs[8][256];  // per-warp (theta*log2e, g) interleaved

    const int lane = threadIdx.x & 31;
    const int wid  = threadIdx.x >> 5;
    const int r    = blockIdx.x * 8 + wid;

    {
        float4 t4 = *reinterpret_cast<const float4*>(th_glob + (size_t)r * kD + lane * 4);
        float4 g4 = *reinterpret_cast<const float4*>(g_glob + (size_t)r * kD + lane * 4);
        float4* d = reinterpret_cast<float4*>(&tgs[wid][lane * 8]);
        d[0] = make_float4(t4.x, g4.x, t4.y, g4.y);
        d[1] = make_float4(t4.z, g4.z, t4.w, g4.w);
    }
    const float* pr = ph_glob + (size_t)r * kD;
    float p0 = pr[lane], p1 = pr[lane + 32], p2 = pr[lane + 64], p3 = pr[lane + 96];
    __syncwarp();

    const float2* tgr = reinterpret_cast<const float2*>(tgs[wid]);
    float n0 = 0.f, n1 = 0.f, n2 = 0.f, n3 = 0.f;
    float d0 = 0.f, d1 = 0.f, d2 = 0.f, d3 = 0.f;
#pragma unroll 8
    for (int j = 0; j < kD; j++) {
        float2 t = tgr[j];
        float e0 = fast_ex2(p0 * t.x);
        float e1 = fast_ex2(p1 * t.x);
        float e2 = fast_ex2(p2 * t.x);
        float e3 = fast_ex2(p3 * t.x);
        d0 += e0; d1 += e1; d2 += e2; d3 += e3;
        n0 = fmaf(e0, t.y, n0);
        n1 = fmaf(e1, t.y, n1);
        n2 = fmaf(e2, t.y, n2);
        n3 = fmaf(e3, t.y, n3);
    }
    float* yr = y_glob + (size_t)r * kD;
    yr[lane]      = __uint_as_float(f2tf(n0 * fast_rcp(d0)));
    yr[lane + 32] = __uint_as_float(f2tf(n1 * fast_rcp(d1)));
    yr[lane + 64] = __uint_as_float(f2tf(n2 * fast_rcp(d2)));
    yr[lane + 96] = __uint_as_float(f2tf(n3 * fast_rcp(d3)));
}

// ========================= K3: out = y@W_w^T + W_b + x0 =========================
__global__ void __launch_bounds__(256, 2)
out_kernel(const float* __restrict__ x0, const float* __restrict__ Ww,
           const float* __restrict__ Wb, float* __restrict__ out) {
    extern __shared__ uint32_t W3[];  // [128][132] tf32 bits

    const int tid  = threadIdx.x;
    const int lane = tid & 31;
    const int wid  = tid >> 5;
    const int gid  = lane >> 2;
    const int tig  = lane & 3;
    const int wm   = wid >> 1;
    const int wn   = wid & 1;
    const int row0 = blockIdx.x * 128;
    const int col0 = blockIdx.y * 128;

#pragma unroll
    for (int i = 0; i < 16; i++) {
        int idx = tid + 256 * i;
        int rr = idx >> 5;
        int cc = idx & 31;
        float4 v = *reinterpret_cast<const float4*>(
            Ww + (size_t)(col0 + rr) * kD + cc * 4);
        sts_tf4(&W3[rr * kW3Str + cc * 4], v);
    }
    __syncthreads();

    float acc[2][8][4];
#pragma unroll
    for (int a = 0; a < 2; a++)
#pragma unroll
        for (int b = 0; b < 8; b++)
#pragma unroll
            for (int c = 0; c < 4; c++) acc[a][b][c] = 0.f;

    const uint32_t* ybase = reinterpret_cast<const uint32_t*>(y_glob);
#pragma unroll 4
    for (int ks = 0; ks < 16; ks++) {
        int k = ks * 8;
        uint32_t a[2][4];
#pragma unroll
        for (int mt = 0; mt < 2; mt++) {
            const uint32_t* yb =
                ybase + (size_t)(row0 + wm * 32 + mt * 16 + gid) * kD + k + tig;
            a[mt][0] = yb[0];
            a[mt][1] = yb[8 * kD];
            a[mt][2] = yb[4];
            a[mt][3] = yb[8 * kD + 4];
        }
#pragma unroll
        for (int nt = 0; nt < 8; nt++) {
            int nb = (wn * 64 + nt * 8 + gid) * kW3Str + k + tig;
            uint32_t b0 = W3[nb];
            uint32_t b1 = W3[nb + 4];
            mma_tf32(acc[0][nt], a[0], b0, b1);
            mma_tf32(acc[1][nt], a[1], b0, b1);
        }
    }

#pragma unroll
    for (int mt = 0; mt < 2; mt++)
#pragma unroll
        for (int nt = 0; nt < 8; nt++)
#pragma unroll
            for (int pair = 0; pair < 2; pair++) {
                int r = wm * 32 + mt * 16 + gid + pair * 8;
                int n = col0 + wn * 64 + nt * 8 + tig * 2;
                float2 xx = *reinterpret_cast<const float2*>(
                    x0 + (size_t)(row0 + r) * kC + n);
                float2 o;
                o.x = acc[mt][nt][pair * 2 + 0] + Wb[n] + xx.x;
                o.y = acc[mt][nt][pair * 2 + 1] + Wb[n + 1] + xx.y;
                *reinterpret_cast<float2*>(out + (size_t)(row0 + r) * kC + n) = o;
            }
}

extern "C" void kernel_launch(void* const* d_in, const int* in_sizes, int n_in,
                              void* d_out, int out_size) {
    (void)in_sizes; (void)n_in; (void)out_size;
    const float* x0   = (const float*)d_in[0];
    const float* x1   = (const float*)d_in[1];
    const float* g_w  = (const float*)d_in[2];
    const float* g_b  = (const float*)d_in[3];
    const float* th_w = (const float*)d_in[4];
    const float* th_b = (const float*)d_in[5];
    const float* ph_w = (const float*)d_in[6];
    const float* ph_b = (const float*)d_in[7];
    const float* Ww   = (const float*)d_in[8];
    const float* Wb   = (const float*)d_in[9];
    float* out = (float*)d_out;

    cudaFuncSetAttribute(proj_kernel,
                         cudaFuncAttributeMaxDynamicSharedMemorySize, kK1Smem);
    cudaFuncSetAttribute(out_kernel,
                         cudaFuncAttributeMaxDynamicSharedMemorySize, kK3Smem);

    conv_w_kernel<<<384, 256>>>(g_w, th_w, ph_w);
    proj_kernel<<<dim3(128, 3), 256, kK1Smem>>>(x0, x1, g_b, th_b, ph_b);
    attn_kernel<<<2048, 256>>>();
    out_kernel<<<dim3(128, 8), 256, kK3Smem>>>(x0, Ww, Wb, out);
}

// round 6
// speedup vs baseline: 1.2251x; 1.2251x over previous
#include <cuda_runtime.h>
#include <cuda_bf16.h>
#include <cstdint>

// ============================================================================
// CrossAttentionBlock — 4-kernel split (sm_100a), permuted-tf32 fragment layout
//   K0: pre-convert weights -> tf32(rna) bits, k-chunk permuted
//       (within each 16-word chunk: word w -> (w&3)*4 + (w>>2), so a thread's
//        mma fragment {tig,tig+4,tig+8,tig+12} is one LDS.128)
//   K1: projections, cp.async 3-stage pipeline, occ 2 (no spills)
//   K2: y_i = sum_j 2^(ph_i*th_j) g_j / sum_j 2^(ph_i*th_j); writes y permuted
//   K3: out = y@W_w^T + W_b + x0; full-K smem tiles, pure LDS.128 feed
// ============================================================================

namespace {
constexpr int kB   = 16384;
constexpr int kC   = 1024;
constexpr int kD   = 128;
constexpr float kLog2e = 1.4426950408889634f;

// K1 smem: A 3 stages of 128x20 words, W 3 stages of 128x16 words (permuted)
constexpr int kAStr     = 20;
constexpr int kAStageW  = 128 * kAStr;        // 2560 words
constexpr int kWStageW  = 128 * 16;           // 2048 words
constexpr int kWBaseW   = 3 * kAStageW;       // 7680
constexpr int kK1Smem   = (3 * kAStageW + 3 * kWStageW) * 4;  // 55296 B

// K3 smem: y [128][144] + W [64][144]  (144 % 32 == 16 -> conflict-free LDS.128)
constexpr int kYStr    = 144;
constexpr int kYWords  = 128 * kYStr;         // 18432
constexpr int kW3Words = 64 * kYStr;          // 9216
constexpr int kK3Smem  = (kYWords + kW3Words) * 4;  // 110592 B
}  // namespace

// inter-kernel scratch
__device__ float    g_glob[kB * kD];
__device__ float    th_glob[kB * kD];        // pre-scaled by log2e
__device__ float    ph_glob[kB * kD];
__device__ float    y_glob[kB * kD];         // tf32 bits, k-chunk permuted
__device__ uint32_t w_glob[3 * kD * kC];     // proj weights tf32, permuted
__device__ uint32_t w3_glob[kC * kD];        // W_w tf32, permuted

__device__ __forceinline__ uint32_t f2tf(float f) {
    uint32_t u;
    asm("cvt.rna.tf32.f32 %0, %1;" : "=r"(u) : "f"(f));
    return u;
}
__device__ __forceinline__ float fast_ex2(float x) {
    float r;
    asm("ex2.approx.ftz.f32 %0, %1;" : "=f"(r) : "f"(x));
    return r;
}
__device__ __forceinline__ float fast_rcp(float x) {
    float r;
    asm("rcp.approx.ftz.f32 %0, %1;" : "=f"(r) : "f"(x));
    return r;
}
__device__ __forceinline__ void mma_tf32(float c[4],
                                         uint32_t a0, uint32_t a1,
                                         uint32_t a2, uint32_t a3,
                                         uint32_t b0, uint32_t b1) {
    asm volatile(
        "mma.sync.aligned.m16n8k8.row.col.f32.tf32.tf32.f32 "
        "{%0,%1,%2,%3},{%4,%5,%6,%7},{%8,%9},{%0,%1,%2,%3};"
        : "+f"(c[0]), "+f"(c[1]), "+f"(c[2]), "+f"(c[3])
        : "r"(a0), "r"(a1), "r"(a2), "r"(a3), "r"(b0), "r"(b1));
}
__device__ __forceinline__ void cp16(uint32_t dst, const void* src) {
    asm volatile("cp.async.cg.shared.global [%0], [%1], 16;" :: "r"(dst), "l"(src));
}
__device__ __forceinline__ void cp_commit() {
    asm volatile("cp.async.commit_group;");
}
template <int N>
__device__ __forceinline__ void cp_wait() {
    asm volatile("cp.async.wait_group %0;" :: "n"(N));
}
__device__ __forceinline__ uint32_t smem_u32(const void* p) {
    uint32_t a;
    asm("{ .reg .u64 t; cvta.to.shared.u64 t, %1; cvt.u32.u64 %0, t; }"
        : "=r"(a) : "l"(p));
    return a;
}
// permuted position of column col (within its 16-word chunk)
__device__ __forceinline__ int permc(int col) {
    return (col & ~15) | ((col & 3) << 2) | ((col >> 2) & 3);
}

// ========== K0: weight pre-convert to permuted tf32 (rna) ==========
// grid 512x256: first 98304 float4 = proj weights (3 heads), last 32768 = W_w.
__global__ void __launch_bounds__(256)
conv_w_kernel(const float* __restrict__ g_w, const float* __restrict__ th_w,
              const float* __restrict__ ph_w, const float* __restrict__ Ww) {
    int i4 = blockIdx.x * 256 + threadIdx.x;
    if (i4 < 98304) {
        int head = i4 >> 15;          // 32768 float4 per head
        int loc  = i4 & 32767;
        const float4* src = (head == 0) ? reinterpret_cast<const float4*>(g_w)
                          : (head == 1) ? reinterpret_cast<const float4*>(th_w)
                                        : reinterpret_cast<const float4*>(ph_w);
        float4 v = src[loc];
        float s = (head == 1) ? kLog2e : 1.0f;
        int wb  = loc * 4;            // word index within head (row*1024+col)
        int col = wb & (kC - 1);
        int q   = (col & 15) >> 2;    // 0..3 (c4/4)
        uint32_t* dst = w_glob + head * kD * kC + (wb & ~15) + q;
        dst[0]  = f2tf(v.x * s);      // col+0 -> pos q
        dst[4]  = f2tf(v.y * s);      // col+1 -> pos q+4
        dst[8]  = f2tf(v.z * s);
        dst[12] = f2tf(v.w * s);
    } else {
        int loc = i4 - 98304;         // 0..32767 float4 of Ww [1024][128]
        float4 v = reinterpret_cast<const float4*>(Ww)[loc];
        int wb  = loc * 4;
        int col = wb & (kD - 1);
        int q   = (col & 15) >> 2;
        uint32_t* dst = w3_glob + (wb & ~15) + q;
        dst[0]  = f2tf(v.x);
        dst[4]  = f2tf(v.y);
        dst[8]  = f2tf(v.z);
        dst[12] = f2tf(v.w);
    }
}

// ========== K1: projections, cp.async 3-stage, tile 128x128, occ 2 ==========
__global__ void __launch_bounds__(256, 2)
proj_kernel(const float* __restrict__ x0, const float* __restrict__ x1,
            const float* __restrict__ g_b, const float* __restrict__ th_b,
            const float* __restrict__ ph_b) {
    extern __shared__ uint32_t sm[];

    const int tid  = threadIdx.x;
    const int lane = tid & 31;
    const int wid  = tid >> 5;
    const int gid  = lane >> 2;
    const int tig  = lane & 3;
    const int wm   = wid >> 1;
    const int wn   = wid & 1;
    const int row0 = blockIdx.x * 128;
    const int by   = blockIdx.y;

    const float* A = (by == 0) ? x0 : x1;
    const uint32_t* W = w_glob + (size_t)by * kD * kC;

    const int r0 = tid >> 2;           // 0..63
    const int c4 = (tid & 3) * 4;      // 0,4,8,12
    const float*    srcA = A + (size_t)(row0 + r0) * kC + c4;
    const uint32_t* srcW = W + (size_t)r0 * kC + c4;
    const uint32_t base = smem_u32(sm);
    const uint32_t dA0 = base + (r0 * kAStr + c4) * 4;
    const uint32_t dW0 = base + (kWBaseW + r0 * 16 + c4) * 4;
    const uint32_t kAHalf = 64 * kAStr * 4;
    const uint32_t kWHalf = 64 * 16 * 4;

    auto issue = [&](int stage, int kc) {
        const float*    pa = srcA + kc * 16;
        const uint32_t* pw = srcW + kc * 16;
        uint32_t sa = stage * (kAStageW * 4);
        uint32_t sw = stage * (kWStageW * 4);
        cp16(dA0 + sa, pa);
        cp16(dA0 + sa + kAHalf, pa + 64 * kC);
        cp16(dW0 + sw, pw);
        cp16(dW0 + sw + kWHalf, pw + 64 * kC);
        cp_commit();
    };

    issue(0, 0);
    issue(1, 1);

    float acc[2][8][4];
#pragma unroll
    for (int a = 0; a < 2; a++)
#pragma unroll
        for (int b = 0; b < 8; b++)
#pragma unroll
            for (int ci = 0; ci < 4; ci++) acc[a][b][ci] = 0.f;

    int buf = 0;
#pragma unroll 1
    for (int kc = 0; kc < 64; kc++) {
        if (kc < 62) cp_wait<1>(); else cp_wait<0>();
        __syncthreads();
        if (kc + 2 < 64) {
            int ns = buf + 2; if (ns >= 3) ns -= 3;
            issue(ns, kc + 2);
        }
        const uint32_t* aS = sm + buf * kAStageW;
        const uint32_t* wS = sm + kWBaseW + buf * kWStageW;

        // A fragments (LDS.32), both k-steps of the chunk
        uint32_t a0[2][4], a1[2][4];
#pragma unroll
        for (int mt = 0; mt < 2; mt++) {
            const uint32_t* p = aS + (wm * 32 + mt * 16 + gid) * kAStr + tig;
            a0[mt][0] = p[0];             a0[mt][1] = p[8 * kAStr];
            a0[mt][2] = p[4];             a0[mt][3] = p[8 * kAStr + 4];
            a1[mt][0] = p[8];             a1[mt][1] = p[8 * kAStr + 8];
            a1[mt][2] = p[12];            a1[mt][3] = p[8 * kAStr + 12];
        }
        // B fragments: one LDS.128 per nt covers both k-steps (permuted layout)
#pragma unroll
        for (int grp = 0; grp < 2; grp++) {
            uint4 bf[4];
#pragma unroll
            for (int j = 0; j < 4; j++) {
                int nt = grp * 4 + j;
                bf[j] = *reinterpret_cast<const uint4*>(
                    wS + (wn * 64 + nt * 8 + gid) * 16 + tig * 4);
            }
#pragma unroll
            for (int j = 0; j < 4; j++) {
                int nt = grp * 4 + j;
                mma_tf32(acc[0][nt], a0[0][0], a0[0][1], a0[0][2], a0[0][3], bf[j].x, bf[j].y);
                mma_tf32(acc[1][nt], a0[1][0], a0[1][1], a0[1][2], a0[1][3], bf[j].x, bf[j].y);
                mma_tf32(acc[0][nt], a1[0][0], a1[0][1], a1[0][2], a1[0][3], bf[j].z, bf[j].w);
                mma_tf32(acc[1][nt], a1[1][0], a1[1][1], a1[1][2], a1[1][3], bf[j].z, bf[j].w);
            }
        }
        buf++; if (buf == 3) buf = 0;
    }

    const float* bias = (by == 0) ? g_b : (by == 1) ? th_b : ph_b;
    const float bscale = (by == 1) ? kLog2e : 1.0f;
    float* outp = (by == 0) ? g_glob : (by == 1) ? th_glob : ph_glob;
#pragma unroll
    for (int mt = 0; mt < 2; mt++)
#pragma unroll
        for (int nt = 0; nt < 8; nt++)
#pragma unroll
            for (int ci = 0; ci < 4; ci++) {
                int r = wm * 32 + mt * 16 + gid + ((ci >= 2) ? 8 : 0);
                int n = wn * 64 + nt * 8 + tig * 2 + (ci & 1);
                outp[(size_t)(row0 + r) * kD + n] =
                    acc[mt][nt][ci] + bias[n] * bscale;
            }
}

// ========================= K2: attention (MUFU-bound) =========================
// grid 2048 x 256; 1 row per warp. Writes y as permuted tf32 bits.
__global__ void __launch_bounds__(256)
attn_kernel() {
    __shared__ float tgs[8][256];

    const int lane = threadIdx.x & 31;
    const int wid  = threadIdx.x >> 5;
    const int r    = blockIdx.x * 8 + wid;

    {
        float4 t4 = *reinterpret_cast<const float4*>(th_glob + (size_t)r * kD + lane * 4);
        float4 g4 = *reinterpret_cast<const float4*>(g_glob + (size_t)r * kD + lane * 4);
        float4* d = reinterpret_cast<float4*>(&tgs[wid][lane * 8]);
        d[0] = make_float4(t4.x, g4.x, t4.y, g4.y);
        d[1] = make_float4(t4.z, g4.z, t4.w, g4.w);
    }
    const float* pr = ph_glob + (size_t)r * kD;
    float p0 = pr[lane], p1 = pr[lane + 32], p2 = pr[lane + 64], p3 = pr[lane + 96];
    __syncwarp();

    const float2* tgr = reinterpret_cast<const float2*>(tgs[wid]);
    float n0 = 0.f, n1 = 0.f, n2 = 0.f, n3 = 0.f;
    float d0 = 0.f, d1 = 0.f, d2 = 0.f, d3 = 0.f;
#pragma unroll 8
    for (int j = 0; j < kD; j++) {
        float2 t = tgr[j];
        float e0 = fast_ex2(p0 * t.x);
        float e1 = fast_ex2(p1 * t.x);
        float e2 = fast_ex2(p2 * t.x);
        float e3 = fast_ex2(p3 * t.x);
        d0 += e0; d1 += e1; d2 += e2; d3 += e3;
        n0 = fmaf(e0, t.y, n0);
        n1 = fmaf(e1, t.y, n1);
        n2 = fmaf(e2, t.y, n2);
        n3 = fmaf(e3, t.y, n3);
    }
    float* yr = y_glob + (size_t)r * kD;
    yr[permc(lane)]      = __uint_as_float(f2tf(n0 * fast_rcp(d0)));
    yr[permc(lane + 32)] = __uint_as_float(f2tf(n1 * fast_rcp(d1)));
    yr[permc(lane + 64)] = __uint_as_float(f2tf(n2 * fast_rcp(d2)));
    yr[permc(lane + 96)] = __uint_as_float(f2tf(n3 * fast_rcp(d3)));
}

// ============ K3: out = y@W_w^T + W_b + x0 — full-K smem, LDS.128 ============
// grid (128 row-tiles, 16 col-tiles), 256 thr, occ 2. Tile 128x64.
__global__ void __launch_bounds__(256, 2)
out_kernel(const float* __restrict__ x0, const float* __restrict__ Wb,
           float* __restrict__ out) {
    extern __shared__ uint32_t sm3[];
    uint32_t* ybuf = sm3;              // [128][144]
    uint32_t* wbuf = sm3 + kYWords;    // [64][144]

    const int tid  = threadIdx.x;
    const int lane = tid & 31;
    const int wid  = tid >> 5;
    const int gid  = lane >> 2;
    const int tig  = lane & 3;
    const int wm   = wid >> 2;         // 0..1  (64 rows each)
    const int wmi  = (wid >> 1) & 1;   // sub row-half: rows wm*64+wmi*32
    const int wn   = wid & 1;          // 0..1  (32 cols each)
    const int row0 = blockIdx.x * 128;
    const int col0 = blockIdx.y * 64;

    const uint32_t base = smem_u32(sm3);
    // stage y tile: 128 rows x 128 words (permuted in y_glob)
    {
        const int rr = tid >> 1;                 // 0..127
        const int cH = (tid & 1) * 16;           // word 0 or 16... need 32 f4/row
        // 128 rows x 32 float4 = 4096 pieces / 256 thr = 16 iters (8 rows/iter)
        const int r8 = tid >> 5;                 // 0..7
        const int cc = (tid & 31) * 4;           // word 0..124
        (void)rr; (void)cH;
#pragma unroll
        for (int i = 0; i < 16; i++) {
            int r = i * 8 + r8;
            cp16(base + (r * kYStr + cc) * 4,
                 y_glob + (size_t)(row0 + r) * kD + cc);
        }
        // stage W tile: 64 rows x 128 words
#pragma unroll
        for (int i = 0; i < 8; i++) {
            int r = i * 8 + r8;
            cp16(base + (kYWords + r * kYStr + cc) * 4,
                 w3_glob + (size_t)(col0 + r) * kD + cc);
        }
        cp_commit();
    }
    cp_wait<0>();
    __syncthreads();

    float acc[2][4][4];   // [mt][nt][4]; warp tile 32 rows x 32 cols
#pragma unroll
    for (int a = 0; a < 2; a++)
#pragma unroll
        for (int b = 0; b < 4; b++)
#pragma unroll
            for (int c = 0; c < 4; c++) acc[a][b][c] = 0.f;

    const int rbase = wm * 64 + wmi * 32;
#pragma unroll
    for (int c = 0; c < 8; c++) {      // 8 chunks of 16 k
        uint4 av[2][2];                // [mt][half]
#pragma unroll
        for (int mt = 0; mt < 2; mt++) {
            int r = rbase + mt * 16 + gid;
            av[mt][0] = *reinterpret_cast<const uint4*>(
                ybuf + r * kYStr + c * 16 + tig * 4);
            av[mt][1] = *reinterpret_cast<const uint4*>(
                ybuf + (r + 8) * kYStr + c * 16 + tig * 4);
        }
        uint4 bv[4];
#pragma unroll
        for (int nt = 0; nt < 4; nt++) {
            int n = wn * 32 + nt * 8 + gid;
            bv[nt] = *reinterpret_cast<const uint4*>(
                wbuf + n * kYStr + c * 16 + tig * 4);
        }
#pragma unroll
        for (int nt = 0; nt < 4; nt++)
#pragma unroll
            for (int mt = 0; mt < 2; mt++) {
                mma_tf32(acc[mt][nt], av[mt][0].x, av[mt][1].x,
                         av[mt][0].y, av[mt][1].y, bv[nt].x, bv[nt].y);
                mma_tf32(acc[mt][nt], av[mt][0].z, av[mt][1].z,
                         av[mt][0].w, av[mt][1].w, bv[nt].z, bv[nt].w);
            }
    }

#pragma unroll
    for (int mt = 0; mt < 2; mt++)
#pragma unroll
        for (int nt = 0; nt < 4; nt++)
#pragma unroll
            for (int pair = 0; pair < 2; pair++) {
                int r = rbase + mt * 16 + gid + pair * 8;
                int n = col0 + wn * 32 + nt * 8 + tig * 2;
                float2 xx = *reinterpret_cast<const float2*>(
                    x0 + (size_t)(row0 + r) * kC + n);
                float2 o;
                o.x = acc[mt][nt][pair * 2 + 0] + Wb[n] + xx.x;
                o.y = acc[mt][nt][pair * 2 + 1] + Wb[n + 1] + xx.y;
                *reinterpret_cast<float2*>(out + (size_t)(row0 + r) * kC + n) = o;
            }
}

extern "C" void kernel_launch(void* const* d_in, const int* in_sizes, int n_in,
                              void* d_out, int out_size) {
    (void)in_sizes; (void)n_in; (void)out_size;
    const float* x0   = (const float*)d_in[0];
    const float* x1   = (const float*)d_in[1];
    const float* g_w  = (const float*)d_in[2];
    const float* g_b  = (const float*)d_in[3];
    const float* th_w = (const float*)d_in[4];
    const float* th_b = (const float*)d_in[5];
    const float* ph_w = (const float*)d_in[6];
    const float* ph_b = (const float*)d_in[7];
    const float* Ww   = (const float*)d_in[8];
    const float* Wb   = (const float*)d_in[9];
    float* out = (float*)d_out;

    cudaFuncSetAttribute(proj_kernel,
                         cudaFuncAttributeMaxDynamicSharedMemorySize, kK1Smem);
    cudaFuncSetAttribute(out_kernel,
                         cudaFuncAttributeMaxDynamicSharedMemorySize, kK3Smem);

    conv_w_kernel<<<512, 256>>>(g_w, th_w, ph_w, Ww);
    proj_kernel<<<dim3(128, 3), 256, kK1Smem>>>(x0, x1, g_b, th_b, ph_b);
    attn_kernel<<<2048, 256>>>();
    out_kernel<<<dim3(128, 16), 256, kK3Smem>>>(x0, Wb, out);
}